// round 2
// baseline (speedup 1.0000x reference)
#include <cuda_runtime.h>
#include <math.h>

// Problem dims
#define NB   128
#define NT   128
#define NC   256
#define NH   4
#define NHS  64
#define NL   6
#define NDFF 1024
#define NV   10000
#define NBT  (NB*NT)

// ---------------------------------------------------------------------------
// Scratch (device globals: no runtime allocation allowed)
// ---------------------------------------------------------------------------
__device__ float g_x  [NBT*NC];   // residual stream
__device__ float g_h  [NBT*NC];   // LN output
__device__ float g_q  [NBT*NC];
__device__ float g_k  [NBT*NC];
__device__ float g_v  [NBT*NC];
__device__ float g_att[NBT*NC];
__device__ float g_ff [NBT*NDFF];

// ---------------------------------------------------------------------------
// Embedding: x[b,t,:] = tok_emb[idx[b,t],:] + pos_emb[t,:]
// ---------------------------------------------------------------------------
__global__ void embed_kernel(const int* __restrict__ idx,
                             const float* __restrict__ tok,
                             const float* __restrict__ pos) {
    int i = blockIdx.x;          // token in [0, NBT)
    int c = threadIdx.x;         // [0, 256)
    int t = i & (NT - 1);
    g_x[i*NC + c] = tok[idx[i]*NC + c] + pos[t*NC + c];
}

// ---------------------------------------------------------------------------
// LayerNorm: warp-per-row (C = 256 -> 8 floats/lane via two float4)
// ---------------------------------------------------------------------------
__global__ void ln_kernel(const float* __restrict__ in, float* __restrict__ out,
                          const float* __restrict__ g, const float* __restrict__ b) {
    int warp = (blockIdx.x * blockDim.x + threadIdx.x) >> 5;
    int lane = threadIdx.x & 31;
    if (warp >= NBT) return;
    const float4* row = (const float4*)(in + (size_t)warp * NC);
    float4 v0 = row[lane];
    float4 v1 = row[lane + 32];
    float s = v0.x+v0.y+v0.z+v0.w + v1.x+v1.y+v1.z+v1.w;
    #pragma unroll
    for (int o = 16; o; o >>= 1) s += __shfl_xor_sync(0xffffffffu, s, o);
    float mean = s * (1.0f / NC);
    float d0x=v0.x-mean, d0y=v0.y-mean, d0z=v0.z-mean, d0w=v0.w-mean;
    float d1x=v1.x-mean, d1y=v1.y-mean, d1z=v1.z-mean, d1w=v1.w-mean;
    float q = d0x*d0x+d0y*d0y+d0z*d0z+d0w*d0w + d1x*d1x+d1y*d1y+d1z*d1z+d1w*d1w;
    #pragma unroll
    for (int o = 16; o; o >>= 1) q += __shfl_xor_sync(0xffffffffu, q, o);
    float rstd = rsqrtf(q * (1.0f / NC) + 1e-5f);
    float4 gg0 = ((const float4*)g)[lane];
    float4 gg1 = ((const float4*)g)[lane + 32];
    float4 bb0 = ((const float4*)b)[lane];
    float4 bb1 = ((const float4*)b)[lane + 32];
    float4 o0, o1;
    o0.x = d0x*rstd*gg0.x + bb0.x;  o0.y = d0y*rstd*gg0.y + bb0.y;
    o0.z = d0z*rstd*gg0.z + bb0.z;  o0.w = d0w*rstd*gg0.w + bb0.w;
    o1.x = d1x*rstd*gg1.x + bb1.x;  o1.y = d1y*rstd*gg1.y + bb1.y;
    o1.z = d1z*rstd*gg1.z + bb1.z;  o1.w = d1w*rstd*gg1.w + bb1.w;
    float4* orow = (float4*)(out + (size_t)warp * NC);
    orow[lane]      = o0;
    orow[lane + 32] = o1;
}

// ---------------------------------------------------------------------------
// Generic fp32 GEMM: out[M,N] = A[M,K] @ W[K,N] (+bias) (+res) (relu)
// BM=BN=64, BK=16, 256 threads, 4x4 microtile.
// Requires M % 64 == 0, K % 16 == 0, N % 4 == 0; N bound-guarded.
// ---------------------------------------------------------------------------
template<bool BIAS, bool RES, bool RELU>
__global__ void gemm_kernel(const float* __restrict__ A, const float* __restrict__ W,
                            const float* __restrict__ bias, const float* __restrict__ res,
                            float* __restrict__ out, int M, int N, int K) {
    __shared__ float As[16][68];   // K-major (transposed) A tile
    __shared__ float Ws[16][68];
    int tid  = threadIdx.x;
    int row0 = blockIdx.y * 64;
    int col0 = blockIdx.x * 64;
    int ty = tid >> 4, tx = tid & 15;

    int la_row = tid >> 2;            // 0..63
    int la_k   = (tid & 3) * 4;       // 0,4,8,12
    int lw_k   = tid >> 4;            // 0..15
    int lw_col = (tid & 15) * 4;      // 0..60

    float acc[4][4] = {};

    for (int k0 = 0; k0 < K; k0 += 16) {
        float4 a4 = *(const float4*)&A[(size_t)(row0 + la_row) * K + k0 + la_k];
        As[la_k + 0][la_row] = a4.x;
        As[la_k + 1][la_row] = a4.y;
        As[la_k + 2][la_row] = a4.z;
        As[la_k + 3][la_row] = a4.w;
        float4 w4;
        if (col0 + lw_col < N)
            w4 = *(const float4*)&W[(size_t)(k0 + lw_k) * N + col0 + lw_col];
        else
            w4 = make_float4(0.f, 0.f, 0.f, 0.f);
        *(float4*)&Ws[lw_k][lw_col] = w4;
        __syncthreads();
        #pragma unroll
        for (int kk = 0; kk < 16; kk++) {
            float4 av = *(const float4*)&As[kk][ty * 4];
            float4 wv = *(const float4*)&Ws[kk][tx * 4];
            acc[0][0] += av.x * wv.x; acc[0][1] += av.x * wv.y;
            acc[0][2] += av.x * wv.z; acc[0][3] += av.x * wv.w;
            acc[1][0] += av.y * wv.x; acc[1][1] += av.y * wv.y;
            acc[1][2] += av.y * wv.z; acc[1][3] += av.y * wv.w;
            acc[2][0] += av.z * wv.x; acc[2][1] += av.z * wv.y;
            acc[2][2] += av.z * wv.z; acc[2][3] += av.z * wv.w;
            acc[3][0] += av.w * wv.x; acc[3][1] += av.w * wv.y;
            acc[3][2] += av.w * wv.z; acc[3][3] += av.w * wv.w;
        }
        __syncthreads();
    }

    #pragma unroll
    for (int i = 0; i < 4; i++) {
        int r = row0 + ty * 4 + i;
        #pragma unroll
        for (int j = 0; j < 4; j++) {
            int c = col0 + tx * 4 + j;
            if (c < N) {
                float vv = acc[i][j];
                if (BIAS) vv += bias[c];
                if (RES)  vv += res[(size_t)r * N + c];
                if (RELU) vv = fmaxf(vv, 0.0f);
                out[(size_t)r * N + c] = vv;
            }
        }
    }
}

// ---------------------------------------------------------------------------
// Causal attention, one (batch, head) per block. q/k/v layout [B,T,H,HS].
// k,v staged in dynamic smem (fp32, 64 KB). Warp-per-query-row online softmax.
// ---------------------------------------------------------------------------
__global__ void attn_kernel(const float* __restrict__ q, const float* __restrict__ k,
                            const float* __restrict__ v, float* __restrict__ att) {
    extern __shared__ float sm[];
    float* ks = sm;               // [T][HS]
    float* vs = sm + NT * NHS;    // [T][HS]
    int bh = blockIdx.x;
    int b = bh / NH, h = bh % NH;
    size_t base = (size_t)(b * NT) * NC + h * NHS;
    int tid = threadIdx.x;

    for (int e = tid; e < NT * NHS / 4; e += 256) {
        int t  = e >> 4;          // e / (HS/4)
        int dq = e & 15;
        ((float4*)ks)[e] = *(const float4*)&k[base + (size_t)t * NC + dq * 4];
        ((float4*)vs)[e] = *(const float4*)&v[base + (size_t)t * NC + dq * 4];
    }
    __syncthreads();

    int warp = tid >> 5, lane = tid & 31;
    const float scale = 0.0625f;   // C^-0.5 = 1/16 (note: C, not head_size)
    for (int tq = warp; tq < NT; tq += 8) {
        float2 qv = *(const float2*)&q[base + (size_t)tq * NC + lane * 2];
        float m = -1e30f, l = 0.f, a0 = 0.f, a1 = 0.f;
        for (int j = 0; j <= tq; j++) {
            float d = qv.x * ks[j*NHS + lane*2] + qv.y * ks[j*NHS + lane*2 + 1];
            #pragma unroll
            for (int o = 16; o; o >>= 1) d += __shfl_xor_sync(0xffffffffu, d, o);
            float s  = d * scale;
            float mn = fmaxf(m, s);
            float cf = __expf(m - mn);
            float p  = __expf(s - mn);
            l  = l * cf + p;
            a0 = a0 * cf + p * vs[j*NHS + lane*2];
            a1 = a1 * cf + p * vs[j*NHS + lane*2 + 1];
            m = mn;
        }
        float inv = 1.0f / l;
        att[base + (size_t)tq * NC + lane*2]     = a0 * inv;
        att[base + (size_t)tq * NC + lane*2 + 1] = a1 * inv;
    }
}

// ---------------------------------------------------------------------------
// Host launcher
// ---------------------------------------------------------------------------
static void launch_gemm_bias(const float* A, const float* W, const float* bias,
                             float* out, int M, int N, int K) {
    dim3 grid((N + 63) / 64, M / 64);
    gemm_kernel<true, false, false><<<grid, 256>>>(A, W, bias, nullptr, out, M, N, K);
}
static void launch_gemm_plain(const float* A, const float* W, float* out,
                              int M, int N, int K) {
    dim3 grid((N + 63) / 64, M / 64);
    gemm_kernel<false, false, false><<<grid, 256>>>(A, W, nullptr, nullptr, out, M, N, K);
}
static void launch_gemm_bias_res(const float* A, const float* W, const float* bias,
                                 const float* res, float* out, int M, int N, int K) {
    dim3 grid((N + 63) / 64, M / 64);
    gemm_kernel<true, true, false><<<grid, 256>>>(A, W, bias, res, out, M, N, K);
}
static void launch_gemm_bias_relu(const float* A, const float* W, const float* bias,
                                  float* out, int M, int N, int K) {
    dim3 grid((N + 63) / 64, M / 64);
    gemm_kernel<true, false, true><<<grid, 256>>>(A, W, bias, nullptr, out, M, N, K);
}

extern "C" void kernel_launch(void* const* d_in, const int* in_sizes, int n_in,
                              void* d_out, int out_size) {
    const int*   idx     = (const int*)  d_in[0];
    const float* tok_emb = (const float*)d_in[1];
    const float* pos_emb = (const float*)d_in[2];
    const float* ln1_g   = (const float*)d_in[3];
    const float* ln1_b   = (const float*)d_in[4];
    const float* wq      = (const float*)d_in[5];
    const float* wk      = (const float*)d_in[6];
    const float* wv      = (const float*)d_in[7];
    const float* proj_w  = (const float*)d_in[8];
    const float* proj_b  = (const float*)d_in[9];
    const float* ln2_g   = (const float*)d_in[10];
    const float* ln2_b   = (const float*)d_in[11];
    const float* w1      = (const float*)d_in[12];
    const float* b1      = (const float*)d_in[13];
    const float* w2      = (const float*)d_in[14];
    const float* b2      = (const float*)d_in[15];
    const float* lnf_g   = (const float*)d_in[16];
    const float* lnf_b   = (const float*)d_in[17];
    const float* lm_w    = (const float*)d_in[18];
    const float* lm_b    = (const float*)d_in[19];
    float* out = (float*)d_out;

    float *x, *h, *q, *k, *v, *att, *ff;
    cudaGetSymbolAddress((void**)&x,   g_x);
    cudaGetSymbolAddress((void**)&h,   g_h);
    cudaGetSymbolAddress((void**)&q,   g_q);
    cudaGetSymbolAddress((void**)&k,   g_k);
    cudaGetSymbolAddress((void**)&v,   g_v);
    cudaGetSymbolAddress((void**)&att, g_att);
    cudaGetSymbolAddress((void**)&ff,  g_ff);

    cudaFuncSetAttribute(attn_kernel, cudaFuncAttributeMaxDynamicSharedMemorySize,
                         2 * NT * NHS * (int)sizeof(float));

    embed_kernel<<<NBT, NC>>>(idx, tok_emb, pos_emb);

    for (int l = 0; l < NL; l++) {
        ln_kernel<<<NBT / 8, 256>>>(x, h, ln1_g + l*NC, ln1_b + l*NC);
        launch_gemm_plain(h, wq + (size_t)l*NC*NC, q, NBT, NC, NC);
        launch_gemm_plain(h, wk + (size_t)l*NC*NC, k, NBT, NC, NC);
        launch_gemm_plain(h, wv + (size_t)l*NC*NC, v, NBT, NC, NC);
        attn_kernel<<<NB * NH, 256, 2 * NT * NHS * (int)sizeof(float)>>>(q, k, v, att);
        launch_gemm_bias_res(att, proj_w + (size_t)l*NC*NC, proj_b + l*NC, x, x,
                             NBT, NC, NC);
        ln_kernel<<<NBT / 8, 256>>>(x, h, ln2_g + l*NC, ln2_b + l*NC);
        launch_gemm_bias_relu(h, w1 + (size_t)l*NC*NDFF, b1 + l*NDFF, ff,
                              NBT, NDFF, NC);
        launch_gemm_bias_res(ff, w2 + (size_t)l*NDFF*NC, b2 + l*NC, x, x,
                             NBT, NC, NDFF);
    }

    ln_kernel<<<NBT / 8, 256>>>(x, h, lnf_g, lnf_b);
    launch_gemm_bias(h, lm_w, lm_b, out, NBT, NV, NC);
}

// round 3
// speedup vs baseline: 2.1871x; 2.1871x over previous
#include <cuda_runtime.h>
#include <math.h>
#include <stdint.h>

// Problem dims
#define NB   128
#define NT   128
#define NC   256
#define NH   4
#define NHS  64
#define NL   6
#define NDFF 1024
#define NV   10000
#define NBT  (NB*NT)

// ---------------------------------------------------------------------------
// Scratch (device globals: no runtime allocation allowed)
// ---------------------------------------------------------------------------
__device__ float g_x  [NBT*NC];   // residual stream
__device__ float g_h  [NBT*NC];   // LN output
__device__ float g_q  [NBT*NC];
__device__ float g_k  [NBT*NC];
__device__ float g_v  [NBT*NC];
__device__ float g_att[NBT*NC];
__device__ float g_ff [NBT*NDFF];

// ---------------------------------------------------------------------------
// Embedding
// ---------------------------------------------------------------------------
__global__ void embed_kernel(const int* __restrict__ idx,
                             const float* __restrict__ tok,
                             const float* __restrict__ pos) {
    int i = blockIdx.x;
    int c = threadIdx.x;
    int t = i & (NT - 1);
    g_x[i*NC + c] = tok[idx[i]*NC + c] + pos[t*NC + c];
}

// ---------------------------------------------------------------------------
// LayerNorm: warp-per-row
// ---------------------------------------------------------------------------
__global__ void ln_kernel(const float* __restrict__ in, float* __restrict__ out,
                          const float* __restrict__ g, const float* __restrict__ b) {
    int warp = (blockIdx.x * blockDim.x + threadIdx.x) >> 5;
    int lane = threadIdx.x & 31;
    if (warp >= NBT) return;
    const float4* row = (const float4*)(in + (size_t)warp * NC);
    float4 v0 = row[lane];
    float4 v1 = row[lane + 32];
    float s = v0.x+v0.y+v0.z+v0.w + v1.x+v1.y+v1.z+v1.w;
    #pragma unroll
    for (int o = 16; o; o >>= 1) s += __shfl_xor_sync(0xffffffffu, s, o);
    float mean = s * (1.0f / NC);
    float d0x=v0.x-mean, d0y=v0.y-mean, d0z=v0.z-mean, d0w=v0.w-mean;
    float d1x=v1.x-mean, d1y=v1.y-mean, d1z=v1.z-mean, d1w=v1.w-mean;
    float q = d0x*d0x+d0y*d0y+d0z*d0z+d0w*d0w + d1x*d1x+d1y*d1y+d1z*d1z+d1w*d1w;
    #pragma unroll
    for (int o = 16; o; o >>= 1) q += __shfl_xor_sync(0xffffffffu, q, o);
    float rstd = rsqrtf(q * (1.0f / NC) + 1e-5f);
    float4 gg0 = ((const float4*)g)[lane];
    float4 gg1 = ((const float4*)g)[lane + 32];
    float4 bb0 = ((const float4*)b)[lane];
    float4 bb1 = ((const float4*)b)[lane + 32];
    float4 o0, o1;
    o0.x = d0x*rstd*gg0.x + bb0.x;  o0.y = d0y*rstd*gg0.y + bb0.y;
    o0.z = d0z*rstd*gg0.z + bb0.z;  o0.w = d0w*rstd*gg0.w + bb0.w;
    o1.x = d1x*rstd*gg1.x + bb1.x;  o1.y = d1y*rstd*gg1.y + bb1.y;
    o1.z = d1z*rstd*gg1.z + bb1.z;  o1.w = d1w*rstd*gg1.w + bb1.w;
    float4* orow = (float4*)(out + (size_t)warp * NC);
    orow[lane]      = o0;
    orow[lane + 32] = o1;
}

// ---------------------------------------------------------------------------
// TF32 tensor-core GEMM: out[M,N] = A[M,K] @ W[K,N] (+bias)(+res)(relu)
// Block tile 128x128, BK=16, 256 threads = 8 warps, warp tile 64x32.
// mma.sync.m16n8k8 tf32. M%128==0, K%16==0, N%4==0 required; N guarded.
// ---------------------------------------------------------------------------
__device__ __forceinline__ uint32_t f2tf32(float x) {
    uint32_t r;
    asm("cvt.rna.tf32.f32 %0, %1;" : "=r"(r) : "f"(x));
    return r;
}

__device__ __forceinline__ void mma_tf32(float* d, const uint32_t* a, const uint32_t* b) {
    asm volatile(
        "mma.sync.aligned.m16n8k8.row.col.f32.tf32.tf32.f32 "
        "{%0,%1,%2,%3}, {%4,%5,%6,%7}, {%8,%9}, {%0,%1,%2,%3};\n"
        : "+f"(d[0]), "+f"(d[1]), "+f"(d[2]), "+f"(d[3])
        : "r"(a[0]), "r"(a[1]), "r"(a[2]), "r"(a[3]), "r"(b[0]), "r"(b[1]));
}

template<bool BIAS, bool RES, bool RELU>
__global__ void __launch_bounds__(256, 2)
mma_gemm(const float* __restrict__ A, const float* __restrict__ W,
         const float* __restrict__ bias, const float* __restrict__ res,
         float* __restrict__ out, int M, int N, int K) {
    __shared__ uint32_t As[128][20];    // [m][k], pad 4 -> conflict-free frag reads
    __shared__ uint32_t Bs[16][136];    // [k][n], pad 8 -> conflict-free frag reads

    int tid  = threadIdx.x;
    int lane = tid & 31;
    int wid  = tid >> 5;
    int row0 = blockIdx.y * 128;
    int col0 = blockIdx.x * 128;
    int wm = (wid & 1) * 64;            // warp row offset in block tile
    int wn = (wid >> 1) * 32;           // warp col offset

    // A global-load mapping: thread loads 2 float4 rows (ar, ar+64) at k-offset ak
    int ar = tid >> 2;                  // 0..63
    int ak = (tid & 3) * 4;             // 0,4,8,12
    // B global-load mapping: rows kk0, kk0+8; cols cc..cc+3
    int kk0 = tid >> 5;                 // 0..7
    int cc  = (tid & 31) * 4;           // 0..124

    float acc[16][4];
    #pragma unroll
    for (int i = 0; i < 16; i++)
        #pragma unroll
        for (int j = 0; j < 4; j++) acc[i][j] = 0.f;

    float4 pa0, pa1, pb0, pb1;
    bool bok = (col0 + cc < N);

    // initial prefetch (k0 = 0)
    pa0 = *(const float4*)&A[(size_t)(row0 + ar) * K + ak];
    pa1 = *(const float4*)&A[(size_t)(row0 + ar + 64) * K + ak];
    pb0 = bok ? *(const float4*)&W[(size_t)kk0 * N + col0 + cc]       : make_float4(0,0,0,0);
    pb1 = bok ? *(const float4*)&W[(size_t)(kk0 + 8) * N + col0 + cc] : make_float4(0,0,0,0);

    for (int k0 = 0; k0 < K; k0 += 16) {
        // store prefetched tile to smem (tf32-converted)
        As[ar][ak+0] = f2tf32(pa0.x); As[ar][ak+1] = f2tf32(pa0.y);
        As[ar][ak+2] = f2tf32(pa0.z); As[ar][ak+3] = f2tf32(pa0.w);
        As[ar+64][ak+0] = f2tf32(pa1.x); As[ar+64][ak+1] = f2tf32(pa1.y);
        As[ar+64][ak+2] = f2tf32(pa1.z); As[ar+64][ak+3] = f2tf32(pa1.w);
        Bs[kk0][cc+0] = f2tf32(pb0.x); Bs[kk0][cc+1] = f2tf32(pb0.y);
        Bs[kk0][cc+2] = f2tf32(pb0.z); Bs[kk0][cc+3] = f2tf32(pb0.w);
        Bs[kk0+8][cc+0] = f2tf32(pb1.x); Bs[kk0+8][cc+1] = f2tf32(pb1.y);
        Bs[kk0+8][cc+2] = f2tf32(pb1.z); Bs[kk0+8][cc+3] = f2tf32(pb1.w);
        __syncthreads();

        // prefetch next tile while computing this one
        if (k0 + 16 < K) {
            int kn = k0 + 16;
            pa0 = *(const float4*)&A[(size_t)(row0 + ar) * K + kn + ak];
            pa1 = *(const float4*)&A[(size_t)(row0 + ar + 64) * K + kn + ak];
            pb0 = bok ? *(const float4*)&W[(size_t)(kn + kk0) * N + col0 + cc]     : make_float4(0,0,0,0);
            pb1 = bok ? *(const float4*)&W[(size_t)(kn + kk0 + 8) * N + col0 + cc] : make_float4(0,0,0,0);
        }

        #pragma unroll
        for (int ks = 0; ks < 16; ks += 8) {
            uint32_t af[4][4], bf[4][2];
            int arow = wm + (lane >> 2);
            int akc  = ks + (lane & 3);
            #pragma unroll
            for (int mt = 0; mt < 4; mt++) {
                af[mt][0] = As[arow + mt*16    ][akc    ];
                af[mt][1] = As[arow + mt*16 + 8][akc    ];
                af[mt][2] = As[arow + mt*16    ][akc + 4];
                af[mt][3] = As[arow + mt*16 + 8][akc + 4];
            }
            #pragma unroll
            for (int nt = 0; nt < 4; nt++) {
                int ncol = wn + nt*8 + (lane >> 2);
                bf[nt][0] = Bs[ks + (lane & 3)    ][ncol];
                bf[nt][1] = Bs[ks + 4 + (lane & 3)][ncol];
            }
            #pragma unroll
            for (int mt = 0; mt < 4; mt++)
                #pragma unroll
                for (int nt = 0; nt < 4; nt++)
                    mma_tf32(acc[mt*4 + nt], af[mt], bf[nt]);
        }
        __syncthreads();
    }

    // epilogue
    #pragma unroll
    for (int mt = 0; mt < 4; mt++) {
        #pragma unroll
        for (int nt = 0; nt < 4; nt++) {
            float* a = acc[mt*4 + nt];
            int r = row0 + wm + mt*16 + (lane >> 2);
            int c = col0 + wn + nt*8 + (lane & 3)*2;
            if (c < N) {
                float b0 = 0.f, b1 = 0.f;
                if (BIAS) { b0 = bias[c]; b1 = bias[c+1]; }
                float v0 = a[0] + b0, v1 = a[1] + b1;
                float v2 = a[2] + b0, v3 = a[3] + b1;
                if (RES) {
                    v0 += res[(size_t)r * N + c];     v1 += res[(size_t)r * N + c + 1];
                    v2 += res[(size_t)(r+8) * N + c]; v3 += res[(size_t)(r+8) * N + c + 1];
                }
                if (RELU) {
                    v0 = fmaxf(v0, 0.f); v1 = fmaxf(v1, 0.f);
                    v2 = fmaxf(v2, 0.f); v3 = fmaxf(v3, 0.f);
                }
                *(float2*)&out[(size_t)r * N + c]     = make_float2(v0, v1);
                *(float2*)&out[(size_t)(r+8) * N + c] = make_float2(v2, v3);
            }
        }
    }
}

// ---------------------------------------------------------------------------
// Causal attention (unchanged from R1)
// ---------------------------------------------------------------------------
__global__ void attn_kernel(const float* __restrict__ q, const float* __restrict__ k,
                            const float* __restrict__ v, float* __restrict__ att) {
    extern __shared__ float sm[];
    float* ks = sm;
    float* vs = sm + NT * NHS;
    int bh = blockIdx.x;
    int b = bh / NH, h = bh % NH;
    size_t base = (size_t)(b * NT) * NC + h * NHS;
    int tid = threadIdx.x;

    for (int e = tid; e < NT * NHS / 4; e += 256) {
        int t  = e >> 4;
        int dq = e & 15;
        ((float4*)ks)[e] = *(const float4*)&k[base + (size_t)t * NC + dq * 4];
        ((float4*)vs)[e] = *(const float4*)&v[base + (size_t)t * NC + dq * 4];
    }
    __syncthreads();

    int warp = tid >> 5, lane = tid & 31;
    const float scale = 0.0625f;   // C^-0.5 (C=256), per reference
    for (int tq = warp; tq < NT; tq += 8) {
        float2 qv = *(const float2*)&q[base + (size_t)tq * NC + lane * 2];
        float m = -1e30f, l = 0.f, a0 = 0.f, a1 = 0.f;
        for (int j = 0; j <= tq; j++) {
            float d = qv.x * ks[j*NHS + lane*2] + qv.y * ks[j*NHS + lane*2 + 1];
            #pragma unroll
            for (int o = 16; o; o >>= 1) d += __shfl_xor_sync(0xffffffffu, d, o);
            float s  = d * scale;
            float mn = fmaxf(m, s);
            float cf = __expf(m - mn);
            float p  = __expf(s - mn);
            l  = l * cf + p;
            a0 = a0 * cf + p * vs[j*NHS + lane*2];
            a1 = a1 * cf + p * vs[j*NHS + lane*2 + 1];
            m = mn;
        }
        float inv = 1.0f / l;
        att[base + (size_t)tq * NC + lane*2]     = a0 * inv;
        att[base + (size_t)tq * NC + lane*2 + 1] = a1 * inv;
    }
}

// ---------------------------------------------------------------------------
// Host launcher
// ---------------------------------------------------------------------------
static inline dim3 gemm_grid(int M, int N) { return dim3((N + 127) / 128, M / 128); }

extern "C" void kernel_launch(void* const* d_in, const int* in_sizes, int n_in,
                              void* d_out, int out_size) {
    const int*   idx     = (const int*)  d_in[0];
    const float* tok_emb = (const float*)d_in[1];
    const float* pos_emb = (const float*)d_in[2];
    const float* ln1_g   = (const float*)d_in[3];
    const float* ln1_b   = (const float*)d_in[4];
    const float* wq      = (const float*)d_in[5];
    const float* wk      = (const float*)d_in[6];
    const float* wv      = (const float*)d_in[7];
    const float* proj_w  = (const float*)d_in[8];
    const float* proj_b  = (const float*)d_in[9];
    const float* ln2_g   = (const float*)d_in[10];
    const float* ln2_b   = (const float*)d_in[11];
    const float* w1      = (const float*)d_in[12];
    const float* b1      = (const float*)d_in[13];
    const float* w2      = (const float*)d_in[14];
    const float* b2      = (const float*)d_in[15];
    const float* lnf_g   = (const float*)d_in[16];
    const float* lnf_b   = (const float*)d_in[17];
    const float* lm_w    = (const float*)d_in[18];
    const float* lm_b    = (const float*)d_in[19];
    float* out = (float*)d_out;

    float *x, *h, *q, *k, *v, *att, *ff;
    cudaGetSymbolAddress((void**)&x,   g_x);
    cudaGetSymbolAddress((void**)&h,   g_h);
    cudaGetSymbolAddress((void**)&q,   g_q);
    cudaGetSymbolAddress((void**)&k,   g_k);
    cudaGetSymbolAddress((void**)&v,   g_v);
    cudaGetSymbolAddress((void**)&att, g_att);
    cudaGetSymbolAddress((void**)&ff,  g_ff);

    cudaFuncSetAttribute(attn_kernel, cudaFuncAttributeMaxDynamicSharedMemorySize,
                         2 * NT * NHS * (int)sizeof(float));

    embed_kernel<<<NBT, NC>>>(idx, tok_emb, pos_emb);

    for (int l = 0; l < NL; l++) {
        ln_kernel<<<NBT / 8, 256>>>(x, h, ln1_g + l*NC, ln1_b + l*NC);
        mma_gemm<false,false,false><<<gemm_grid(NBT, NC), 256>>>(
            h, wq + (size_t)l*NC*NC, nullptr, nullptr, q, NBT, NC, NC);
        mma_gemm<false,false,false><<<gemm_grid(NBT, NC), 256>>>(
            h, wk + (size_t)l*NC*NC, nullptr, nullptr, k, NBT, NC, NC);
        mma_gemm<false,false,false><<<gemm_grid(NBT, NC), 256>>>(
            h, wv + (size_t)l*NC*NC, nullptr, nullptr, v, NBT, NC, NC);
        attn_kernel<<<NB * NH, 256, 2 * NT * NHS * (int)sizeof(float)>>>(q, k, v, att);
        mma_gemm<true,true,false><<<gemm_grid(NBT, NC), 256>>>(
            att, proj_w + (size_t)l*NC*NC, proj_b + l*NC, x, x, NBT, NC, NC);
        ln_kernel<<<NBT / 8, 256>>>(x, h, ln2_g + l*NC, ln2_b + l*NC);
        mma_gemm<true,false,true><<<gemm_grid(NBT, NDFF), 256>>>(
            h, w1 + (size_t)l*NC*NDFF, b1 + l*NDFF, nullptr, ff, NBT, NDFF, NC);
        mma_gemm<true,true,false><<<gemm_grid(NBT, NC), 256>>>(
            ff, w2 + (size_t)l*NDFF*NC, b2 + l*NC, x, x, NBT, NC, NDFF);
    }

    ln_kernel<<<NBT / 8, 256>>>(x, h, lnf_g, lnf_b);
    mma_gemm<true,false,false><<<gemm_grid(NBT, NV), 256>>>(
        h, lm_w, lm_b, nullptr, out, NBT, NV, NC);
}

// round 7
// speedup vs baseline: 2.4354x; 1.1135x over previous
#include <cuda_runtime.h>
#include <math.h>
#include <stdint.h>

// Problem dims
#define NB   128
#define NT   128
#define NC   256
#define NH   4
#define NHS  64
#define NL   6
#define NDFF 1024
#define NV   10000
#define NBT  (NB*NT)
#define NQKV (3*NC)   // 768

// ---------------------------------------------------------------------------
// Scratch (device globals)
// ---------------------------------------------------------------------------
__device__ float g_x  [NBT*NC];     // residual stream
__device__ float g_h  [NBT*NC];     // LN output (tf32-rounded)
__device__ float g_qkv[NBT*NQKV];   // fused qkv
__device__ float g_att[NBT*NC];     // attention out (tf32-rounded)
__device__ float g_ff [NBT*NDFF];   // MLP hidden (tf32-rounded)
// tf32-pre-rounded weights
__device__ float g_wqkv [NL*NC*NQKV];
__device__ float g_projw[NL*NC*NC];
__device__ float g_w1   [NL*NC*NDFF];
__device__ float g_w2   [NL*NDFF*NC];
__device__ float g_lmw  [NC*NV];

__device__ __forceinline__ uint32_t f2tf32(float x) {
    uint32_t r;
    asm("cvt.rna.tf32.f32 %0, %1;" : "=r"(r) : "f"(x));
    return r;
}
__device__ __forceinline__ float tf32r(float x) { return __uint_as_float(f2tf32(x)); }

// ---------------------------------------------------------------------------
// Weight pre-rounding / packing (runs once per replay; ~30MB traffic)
// ---------------------------------------------------------------------------
__global__ void pack_qkv_kernel(const float* __restrict__ wq,
                                const float* __restrict__ wk,
                                const float* __restrict__ wv) {
    int e = blockIdx.x * 256 + threadIdx.x;        // < NL*NC*NC
    int l = e / (NC*NC);
    int rc = e % (NC*NC);
    int r = rc / NC, c = rc % NC;
    float* dst = g_wqkv + (size_t)(l*NC + r) * NQKV;
    dst[c]          = tf32r(wq[e]);
    dst[NC + c]     = tf32r(wk[e]);
    dst[2*NC + c]   = tf32r(wv[e]);
}
__global__ void round_kernel(const float* __restrict__ in, float* __restrict__ out, int n4) {
    int i = blockIdx.x * 256 + threadIdx.x;
    if (i < n4) {
        float4 v = ((const float4*)in)[i];
        v.x = tf32r(v.x); v.y = tf32r(v.y); v.z = tf32r(v.z); v.w = tf32r(v.w);
        ((float4*)out)[i] = v;
    }
}

// ---------------------------------------------------------------------------
// Embedding
// ---------------------------------------------------------------------------
__global__ void embed_kernel(const int* __restrict__ idx,
                             const float* __restrict__ tok,
                             const float* __restrict__ pos) {
    int i = blockIdx.x;
    int c = threadIdx.x;
    int t = i & (NT - 1);
    g_x[i*NC + c] = tok[idx[i]*NC + c] + pos[t*NC + c];
}

// ---------------------------------------------------------------------------
// LayerNorm: warp-per-row; output tf32-rounded (feeds MMA GEMMs)
// ---------------------------------------------------------------------------
__global__ void ln_kernel(const float* __restrict__ in, float* __restrict__ out,
                          const float* __restrict__ g, const float* __restrict__ b) {
    int warp = (blockIdx.x * blockDim.x + threadIdx.x) >> 5;
    int lane = threadIdx.x & 31;
    if (warp >= NBT) return;
    const float4* row = (const float4*)(in + (size_t)warp * NC);
    float4 v0 = row[lane];
    float4 v1 = row[lane + 32];
    float s = v0.x+v0.y+v0.z+v0.w + v1.x+v1.y+v1.z+v1.w;
    #pragma unroll
    for (int o = 16; o; o >>= 1) s += __shfl_xor_sync(0xffffffffu, s, o);
    float mean = s * (1.0f / NC);
    float d0x=v0.x-mean, d0y=v0.y-mean, d0z=v0.z-mean, d0w=v0.w-mean;
    float d1x=v1.x-mean, d1y=v1.y-mean, d1z=v1.z-mean, d1w=v1.w-mean;
    float q = d0x*d0x+d0y*d0y+d0z*d0z+d0w*d0w + d1x*d1x+d1y*d1y+d1z*d1z+d1w*d1w;
    #pragma unroll
    for (int o = 16; o; o >>= 1) q += __shfl_xor_sync(0xffffffffu, q, o);
    float rstd = rsqrtf(q * (1.0f / NC) + 1e-5f);
    float4 gg0 = ((const float4*)g)[lane];
    float4 gg1 = ((const float4*)g)[lane + 32];
    float4 bb0 = ((const float4*)b)[lane];
    float4 bb1 = ((const float4*)b)[lane + 32];
    float4 o0, o1;
    o0.x = tf32r(d0x*rstd*gg0.x + bb0.x);  o0.y = tf32r(d0y*rstd*gg0.y + bb0.y);
    o0.z = tf32r(d0z*rstd*gg0.z + bb0.z);  o0.w = tf32r(d0w*rstd*gg0.w + bb0.w);
    o1.x = tf32r(d1x*rstd*gg1.x + bb1.x);  o1.y = tf32r(d1y*rstd*gg1.y + bb1.y);
    o1.z = tf32r(d1z*rstd*gg1.z + bb1.z);  o1.w = tf32r(d1w*rstd*gg1.w + bb1.w);
    float4* orow = (float4*)(out + (size_t)warp * NC);
    orow[lane]      = o0;
    orow[lane + 32] = o1;
}

// ---------------------------------------------------------------------------
// TF32 MMA GEMM, cp.async double-buffered. Inputs pre-rounded to tf32.
// Block tile 128x128, BK=32, 256 threads, warp tile 64x32 (m16n8k8).
// ---------------------------------------------------------------------------
__device__ __forceinline__ void mma_tf32(float* d, const uint32_t* a, const uint32_t* b) {
    asm volatile(
        "mma.sync.aligned.m16n8k8.row.col.f32.tf32.tf32.f32 "
        "{%0,%1,%2,%3}, {%4,%5,%6,%7}, {%8,%9}, {%0,%1,%2,%3};\n"
        : "+f"(d[0]), "+f"(d[1]), "+f"(d[2]), "+f"(d[3])
        : "r"(a[0]), "r"(a[1]), "r"(a[2]), "r"(a[3]), "r"(b[0]), "r"(b[1]));
}
__device__ __forceinline__ void cp16(float* dst, const float* src, bool ok) {
    uint32_t s = (uint32_t)__cvta_generic_to_shared(dst);
    int sz = ok ? 16 : 0;
    asm volatile("cp.async.cg.shared.global [%0], [%1], 16, %2;\n"
                 :: "r"(s), "l"(src), "r"(sz));
}

#define GEMM_SMEM ((2*128*36 + 2*32*136) * 4)   // 71680 bytes

template<bool BIAS, bool RES, bool RELU, bool ROUND>
__global__ void __launch_bounds__(256, 2)
mma_gemm(const float* __restrict__ A, const float* __restrict__ W,
         const float* __restrict__ bias, const float* __restrict__ res,
         float* __restrict__ out, int M, int N, int K) {
    extern __shared__ float smem[];
    float (*As)[128][36] = reinterpret_cast<float (*)[128][36]>(smem);
    float (*Bs)[32][136] = reinterpret_cast<float (*)[32][136]>(smem + 2*128*36);

    int tid  = threadIdx.x;
    int lane = tid & 31;
    int wid  = tid >> 5;
    int row0 = blockIdx.y * 128;
    int col0 = blockIdx.x * 128;
    int wm = (wid & 1) * 64;
    int wn = (wid >> 1) * 32;

    float acc[16][4];
    #pragma unroll
    for (int i = 0; i < 16; i++)
        #pragma unroll
        for (int j = 0; j < 4; j++) acc[i][j] = 0.f;

    auto load_stage = [&](int s, int k0) {
        #pragma unroll
        for (int i = 0; i < 4; i++) {
            int lin = tid + i * 256;
            int r = lin >> 3, kq = (lin & 7) * 4;
            cp16(&As[s][r][kq], &A[(size_t)(row0 + r) * K + k0 + kq], true);
        }
        #pragma unroll
        for (int i = 0; i < 4; i++) {
            int lin = tid + i * 256;
            int kr = lin >> 5, cc = (lin & 31) * 4;
            cp16(&Bs[s][kr][cc], &W[(size_t)(k0 + kr) * N + col0 + cc], col0 + cc < N);
        }
        asm volatile("cp.async.commit_group;\n");
    };

    int nk = K >> 5;
    load_stage(0, 0);
    for (int i = 0; i < nk; i++) {
        int buf = i & 1;
        if (i + 1 < nk) {
            load_stage(buf ^ 1, (i + 1) << 5);
            asm volatile("cp.async.wait_group 1;\n");
        } else {
            asm volatile("cp.async.wait_group 0;\n");
        }
        __syncthreads();

        #pragma unroll
        for (int ks = 0; ks < 32; ks += 8) {
            uint32_t af[4][4], bf[4][2];
            int arow = wm + (lane >> 2);
            int akc  = ks + (lane & 3);
            #pragma unroll
            for (int mt = 0; mt < 4; mt++) {
                af[mt][0] = __float_as_uint(As[buf][arow + mt*16    ][akc    ]);
                af[mt][1] = __float_as_uint(As[buf][arow + mt*16 + 8][akc    ]);
                af[mt][2] = __float_as_uint(As[buf][arow + mt*16    ][akc + 4]);
                af[mt][3] = __float_as_uint(As[buf][arow + mt*16 + 8][akc + 4]);
            }
            #pragma unroll
            for (int nt = 0; nt < 4; nt++) {
                int ncol = wn + nt*8 + (lane >> 2);
                bf[nt][0] = __float_as_uint(Bs[buf][ks + (lane & 3)    ][ncol]);
                bf[nt][1] = __float_as_uint(Bs[buf][ks + 4 + (lane & 3)][ncol]);
            }
            #pragma unroll
            for (int mt = 0; mt < 4; mt++)
                #pragma unroll
                for (int nt = 0; nt < 4; nt++)
                    mma_tf32(acc[mt*4 + nt], af[mt], bf[nt]);
        }
        __syncthreads();
    }

    // epilogue
    #pragma unroll
    for (int mt = 0; mt < 4; mt++) {
        #pragma unroll
        for (int nt = 0; nt < 4; nt++) {
            float* a = acc[mt*4 + nt];
            int r = row0 + wm + mt*16 + (lane >> 2);
            int c = col0 + wn + nt*8 + (lane & 3)*2;
            if (c < N) {
                float b0 = 0.f, b1 = 0.f;
                if (BIAS) { b0 = bias[c]; b1 = bias[c+1]; }
                float v0 = a[0] + b0, v1 = a[1] + b1;
                float v2 = a[2] + b0, v3 = a[3] + b1;
                if (RES) {
                    v0 += res[(size_t)r * N + c];     v1 += res[(size_t)r * N + c + 1];
                    v2 += res[(size_t)(r+8) * N + c]; v3 += res[(size_t)(r+8) * N + c + 1];
                }
                if (RELU) {
                    v0 = fmaxf(v0, 0.f); v1 = fmaxf(v1, 0.f);
                    v2 = fmaxf(v2, 0.f); v3 = fmaxf(v3, 0.f);
                }
                if (ROUND) {
                    v0 = tf32r(v0); v1 = tf32r(v1); v2 = tf32r(v2); v3 = tf32r(v3);
                }
                *(float2*)&out[(size_t)r * N + c]     = make_float2(v0, v1);
                *(float2*)&out[(size_t)(r+8) * N + c] = make_float2(v2, v3);
            }
        }
    }
}

// ---------------------------------------------------------------------------
// Causal attention: reads fused qkv [NBT][768]; writes att [NBT][256] rounded.
// ---------------------------------------------------------------------------
__global__ void attn_kernel(const float* __restrict__ qkv, float* __restrict__ att) {
    extern __shared__ float sm[];
    float* ks = sm;
    float* vs = sm + NT * NHS;
    int bh = blockIdx.x;
    int b = bh / NH, h = bh % NH;
    size_t rbase = (size_t)(b * NT) * NQKV + h * NHS;
    int tid = threadIdx.x;

    for (int e = tid; e < NT * NHS / 4; e += 256) {
        int t  = e >> 4;
        int dq = e & 15;
        ((float4*)ks)[e] = *(const float4*)&qkv[rbase + NC   + (size_t)t * NQKV + dq * 4];
        ((float4*)vs)[e] = *(const float4*)&qkv[rbase + 2*NC + (size_t)t * NQKV + dq * 4];
    }
    __syncthreads();

    int warp = tid >> 5, lane = tid & 31;
    const float scale = 0.0625f;   // C^-0.5 (C=256), per reference
    for (int tq = warp; tq < NT; tq += 8) {
        float2 qv = *(const float2*)&qkv[rbase + (size_t)tq * NQKV + lane * 2];
        float m = -1e30f, l = 0.f, a0 = 0.f, a1 = 0.f;
        for (int j = 0; j <= tq; j++) {
            float d = qv.x * ks[j*NHS + lane*2] + qv.y * ks[j*NHS + lane*2 + 1];
            #pragma unroll
            for (int o = 16; o; o >>= 1) d += __shfl_xor_sync(0xffffffffu, d, o);
            float s  = d * scale;
            float mn = fmaxf(m, s);
            float cf = __expf(m - mn);
            float p  = __expf(s - mn);
            l  = l * cf + p;
            a0 = a0 * cf + p * vs[j*NHS + lane*2];
            a1 = a1 * cf + p * vs[j*NHS + lane*2 + 1];
            m = mn;
        }
        float inv = 1.0f / l;
        size_t obase = (size_t)(b * NT + tq) * NC + h * NHS;
        att[obase + lane*2]     = tf32r(a0 * inv);
        att[obase + lane*2 + 1] = tf32r(a1 * inv);
    }
}

// ---------------------------------------------------------------------------
// Host launcher
// ---------------------------------------------------------------------------
extern "C" void kernel_launch(void* const* d_in, const int* in_sizes, int n_in,
                              void* d_out, int out_size) {
    const int*   idx     = (const int*)  d_in[0];
    const float* tok_emb = (const float*)d_in[1];
    const float* pos_emb = (const float*)d_in[2];
    const float* ln1_g   = (const float*)d_in[3];
    const float* ln1_b   = (const float*)d_in[4];
    const float* wq      = (const float*)d_in[5];
    const float* wk      = (const float*)d_in[6];
    const float* wv      = (const float*)d_in[7];
    const float* proj_w  = (const float*)d_in[8];
    const float* proj_b  = (const float*)d_in[9];
    const float* ln2_g   = (const float*)d_in[10];
    const float* ln2_b   = (const float*)d_in[11];
    const float* w1      = (const float*)d_in[12];
    const float* b1      = (const float*)d_in[13];
    const float* w2      = (const float*)d_in[14];
    const float* b2      = (const float*)d_in[15];
    const float* lnf_g   = (const float*)d_in[16];
    const float* lnf_b   = (const float*)d_in[17];
    const float* lm_w    = (const float*)d_in[18];
    const float* lm_b    = (const float*)d_in[19];
    float* out = (float*)d_out;

    float *x, *h, *qkv, *att, *ff;
    float *wqkv, *projw, *pw1, *pw2, *lmw;
    cudaGetSymbolAddress((void**)&x,    g_x);
    cudaGetSymbolAddress((void**)&h,    g_h);
    cudaGetSymbolAddress((void**)&qkv,  g_qkv);
    cudaGetSymbolAddress((void**)&att,  g_att);
    cudaGetSymbolAddress((void**)&ff,   g_ff);
    cudaGetSymbolAddress((void**)&wqkv, g_wqkv);
    cudaGetSymbolAddress((void**)&projw,g_projw);
    cudaGetSymbolAddress((void**)&pw1,  g_w1);
    cudaGetSymbolAddress((void**)&pw2,  g_w2);
    cudaGetSymbolAddress((void**)&lmw,  g_lmw);

    cudaFuncSetAttribute(attn_kernel, cudaFuncAttributeMaxDynamicSharedMemorySize,
                         2 * NT * NHS * (int)sizeof(float));
    cudaFuncSetAttribute(mma_gemm<false,false,false,false>,
                         cudaFuncAttributeMaxDynamicSharedMemorySize, GEMM_SMEM);
    cudaFuncSetAttribute(mma_gemm<true,true,false,false>,
                         cudaFuncAttributeMaxDynamicSharedMemorySize, GEMM_SMEM);
    cudaFuncSetAttribute(mma_gemm<true,false,true,true>,
                         cudaFuncAttributeMaxDynamicSharedMemorySize, GEMM_SMEM);
    cudaFuncSetAttribute(mma_gemm<true,false,false,false>,
                         cudaFuncAttributeMaxDynamicSharedMemorySize, GEMM_SMEM);

    // ---- weight pre-round / pack ----
    pack_qkv_kernel<<<(NL*NC*NC)/256, 256>>>(wq, wk, wv);
    round_kernel<<<(NL*NC*NC/4 + 255)/256, 256>>>(proj_w, projw, NL*NC*NC/4);
    round_kernel<<<(NL*NC*NDFF/4 + 255)/256, 256>>>(w1, pw1, NL*NC*NDFF/4);
    round_kernel<<<(NL*NDFF*NC/4 + 255)/256, 256>>>(w2, pw2, NL*NDFF*NC/4);
    round_kernel<<<(NC*NV/4 + 255)/256, 256>>>(lm_w, lmw, NC*NV/4);

    embed_kernel<<<NBT, NC>>>(idx, tok_emb, pos_emb);

    for (int l = 0; l < NL; l++) {
        ln_kernel<<<NBT / 8, 256>>>(x, h, ln1_g + l*NC, ln1_b + l*NC);
        mma_gemm<false,false,false,false><<<dim3(NQKV/128, NBT/128), 256, GEMM_SMEM>>>(
            h, wqkv + (size_t)l*NC*NQKV, nullptr, nullptr, qkv, NBT, NQKV, NC);
        attn_kernel<<<NB * NH, 256, 2 * NT * NHS * (int)sizeof(float)>>>(qkv, att);
        mma_gemm<true,true,false,false><<<dim3(NC/128, NBT/128), 256, GEMM_SMEM>>>(
            att, projw + (size_t)l*NC*NC, proj_b + l*NC, x, x, NBT, NC, NC);
        ln_kernel<<<NBT / 8, 256>>>(x, h, ln2_g + l*NC, ln2_b + l*NC);
        mma_gemm<true,false,true,true><<<dim3(NDFF/128, NBT/128), 256, GEMM_SMEM>>>(
            h, pw1 + (size_t)l*NC*NDFF, b1 + l*NDFF, nullptr, ff, NBT, NDFF, NC);
        mma_gemm<true,true,false,false><<<dim3(NC/128, NBT/128), 256, GEMM_SMEM>>>(
            ff, pw2 + (size_t)l*NDFF*NC, b2 + l*NC, x, x, NBT, NC, NDFF);
    }

    ln_kernel<<<NBT / 8, 256>>>(x, h, lnf_g, lnf_b);
    mma_gemm<true,false,false,false><<<dim3((NV + 127)/128, NBT/128), 256, GEMM_SMEM>>>(
        h, lmw, lm_b, nullptr, out, NBT, NV, NC);
}